// round 1
// baseline (speedup 1.0000x reference)
#include <cuda_runtime.h>

// Problem constants (match reference)
#define BATCH 8
#define HH 1024
#define WW 1024
#define NPIX (BATCH * HH * WW)

static __device__ float g_u[NPIX];  // u state (in-place updated)
static __device__ float g_q[NPIX];  // q state (in-place updated)

__device__ __forceinline__ float sigmoidf_fast(float x) {
    return 1.0f / (1.0f + __expf(-x));
}

// ---------------------------------------------------------------------------
// K0: u = sigmoid(o / EPS), q = 0.   EPS = 0.5 -> multiply by 2.
// One row per CTA, 4 px per thread.
// ---------------------------------------------------------------------------
__global__ void k_init(const float* __restrict__ o) {
    const int i = blockIdx.x;            // row
    const int b = blockIdx.y;            // batch
    const int j = threadIdx.x << 2;      // col
    const int idx = (b * HH + i) * WW + j;

    float4 o4 = *reinterpret_cast<const float4*>(o + idx);
    float4 u4;
    u4.x = sigmoidf_fast(o4.x * 2.0f);
    u4.y = sigmoidf_fast(o4.y * 2.0f);
    u4.z = sigmoidf_fast(o4.z * 2.0f);
    u4.w = sigmoidf_fast(o4.w * 2.0f);
    *reinterpret_cast<float4*>(g_u + idx) = u4;
    *reinterpret_cast<float4*>(g_q + idx) = make_float4(0.f, 0.f, 0.f, 0.f);
}

// ---------------------------------------------------------------------------
// K1 (q-step):
//   gx = u[i+1,j]-u[i,j] (0-pad below), gy = u[i,j+1]-u[i,j] (0-pad right)
//   q  = max(q - TAU*(gx*vf1 + gy*vf0), 0)          TAU = 0.5
// vf layout: (H, W, 2) interleaved -> vf[(i*W+j)*2 + 0] = vf0, +1 = vf1
// In-place on q: each element reads only its own q. u untouched.
// ---------------------------------------------------------------------------
__global__ void k_qstep(const float* __restrict__ vf) {
    const int i = blockIdx.x;
    const int b = blockIdx.y;
    const int j = threadIdx.x << 2;
    const int idx = (b * HH + i) * WW + j;

    float4 u4 = *reinterpret_cast<const float4*>(g_u + idx);
    float4 un4 = make_float4(0.f, 0.f, 0.f, 0.f);
    if (i + 1 < HH) un4 = *reinterpret_cast<const float4*>(g_u + idx + WW);
    float ur = (j + 4 < WW) ? g_u[idx + 4] : 0.0f;

    float4 q4 = *reinterpret_cast<const float4*>(g_q + idx);

    const float4* vfp = reinterpret_cast<const float4*>(vf + (size_t)(i * WW + j) * 2);
    float4 v01 = vfp[0];   // vf0[j], vf1[j], vf0[j+1], vf1[j+1]
    float4 v23 = vfp[1];   // vf0[j+2], vf1[j+2], vf0[j+3], vf1[j+3]

    // vertical forward diffs
    float gx0 = un4.x - u4.x, gx1 = un4.y - u4.y, gx2 = un4.z - u4.z, gx3 = un4.w - u4.w;
    // horizontal forward diffs
    float gy0 = u4.y - u4.x, gy1 = u4.z - u4.y, gy2 = u4.w - u4.z, gy3 = ur - u4.w;

    q4.x = fmaxf(q4.x - 0.5f * (gx0 * v01.y + gy0 * v01.x), 0.0f);
    q4.y = fmaxf(q4.y - 0.5f * (gx1 * v01.w + gy1 * v01.z), 0.0f);
    q4.z = fmaxf(q4.z - 0.5f * (gx2 * v23.y + gy2 * v23.x), 0.0f);
    q4.w = fmaxf(q4.w - 0.5f * (gx3 * v23.w + gy3 * v23.z), 0.0f);

    *reinterpret_cast<float4*>(g_q + idx) = q4;
}

// ---------------------------------------------------------------------------
// K2 (u-step / final):
//   p0 = vf1*q, p1 = vf0*q
//   Tq = p0[i,j]-p0[i-1,j] + p1[i,j]-p1[i,j-1]   (0-pad top/left)
//   FINAL=0: u = sigmoid((o-Tq)*2)   FINAL=1: out = (o-Tq)*2
// In-place on u: this kernel never reads u.
// ---------------------------------------------------------------------------
template <bool FINAL>
__global__ void k_ustep(const float* __restrict__ o,
                        const float* __restrict__ vf,
                        float* __restrict__ out) {
    const int i = blockIdx.x;
    const int b = blockIdx.y;
    const int j = threadIdx.x << 2;
    const int idx = (b * HH + i) * WW + j;

    float4 q4 = *reinterpret_cast<const float4*>(g_q + idx);

    float4 qu4 = make_float4(0.f, 0.f, 0.f, 0.f);
    float4 vu01 = make_float4(0.f, 0.f, 0.f, 0.f);
    float4 vu23 = make_float4(0.f, 0.f, 0.f, 0.f);
    if (i > 0) {
        qu4 = *reinterpret_cast<const float4*>(g_q + idx - WW);
        const float4* vfu = reinterpret_cast<const float4*>(vf + (size_t)((i - 1) * WW + j) * 2);
        vu01 = vfu[0];
        vu23 = vfu[1];
    }

    float ql = 0.f, vfl0 = 0.f;
    if (j > 0) {
        ql   = g_q[idx - 1];
        vfl0 = vf[(size_t)(i * WW + j - 1) * 2 + 0];
    }

    const float4* vfp = reinterpret_cast<const float4*>(vf + (size_t)(i * WW + j) * 2);
    float4 v01 = vfp[0];
    float4 v23 = vfp[1];

    // Tq per pixel: p0 - p0_up + p1 - p1_left
    float Tq0 = v01.y * q4.x - vu01.y * qu4.x + v01.x * q4.x - vfl0  * ql;
    float Tq1 = v01.w * q4.y - vu01.w * qu4.y + v01.z * q4.y - v01.x * q4.x;
    float Tq2 = v23.y * q4.z - vu23.y * qu4.z + v23.x * q4.z - v01.z * q4.y;
    float Tq3 = v23.w * q4.w - vu23.w * qu4.w + v23.z * q4.w - v23.x * q4.z;

    float4 o4 = *reinterpret_cast<const float4*>(o + idx);
    float x0 = (o4.x - Tq0) * 2.0f;
    float x1 = (o4.y - Tq1) * 2.0f;
    float x2 = (o4.z - Tq2) * 2.0f;
    float x3 = (o4.w - Tq3) * 2.0f;

    if (FINAL) {
        *reinterpret_cast<float4*>(out + idx) = make_float4(x0, x1, x2, x3);
    } else {
        float4 u4;
        u4.x = sigmoidf_fast(x0);
        u4.y = sigmoidf_fast(x1);
        u4.z = sigmoidf_fast(x2);
        u4.w = sigmoidf_fast(x3);
        *reinterpret_cast<float4*>(g_u + idx) = u4;
    }
}

// ---------------------------------------------------------------------------
// Launch: init + 10 x (q-step, u-step); last u-step writes d_out = (o-Tq)/EPS
// Inputs (metadata order): o [8*1024*1024], vector_field [1024*1024*2],
//                          nabla_w [18], div_w [18] (constants, hard-coded)
// ---------------------------------------------------------------------------
extern "C" void kernel_launch(void* const* d_in, const int* in_sizes, int n_in,
                              void* d_out, int out_size) {
    const float* o  = (const float*)d_in[0];
    const float* vf = (const float*)d_in[1];
    float* out = (float*)d_out;

    dim3 grid(HH, BATCH);
    dim3 block(WW / 4);  // 256 threads, 4 px each = one row

    k_init<<<grid, block>>>(o);
    for (int it = 0; it < 10; ++it) {
        k_qstep<<<grid, block>>>(vf);
        if (it < 9)
            k_ustep<false><<<grid, block>>>(o, vf, out);
        else
            k_ustep<true><<<grid, block>>>(o, vf, out);
    }
}

// round 2
// speedup vs baseline: 1.4535x; 1.4535x over previous
#include <cuda_runtime.h>

#define BATCH 8
#define HH 1024
#define WW 1024

#define TILE 104          // valid output span per tile dim
#define HALO 12           // >= 10 needed; 12 keeps float4 alignment
#define EXT  128          // TILE + 2*HALO
#define NWARP 8
#define RPW  16           // rows per warp (NWARP*RPW == EXT)
#define NT   256
#define NITER 10

#define SMEM_BYTES ((2*EXT*EXT + 2*NWARP*EXT) * 4)

__device__ __forceinline__ float sigm(float x) {
    return __fdividef(1.0f, 1.0f + __expf(-x));
}

__global__ void __launch_bounds__(NT, 1)
ccs_fused(const float* __restrict__ o, const float* __restrict__ vf,
          float* __restrict__ out) {
    extern __shared__ float sm[];
    float* sv0 = sm;                    // vf0 [EXT][EXT] (zeroed outside image)
    float* sv1 = sm + EXT * EXT;        // vf1 [EXT][EXT]
    float* xu  = sm + 2 * EXT * EXT;    // per-warp u top-row exchange [NWARP][EXT]
    float* xq  = xu + NWARP * EXT;      // per-warp q bottom-row exchange

    const int tid  = threadIdx.x;
    const int w    = tid >> 5;
    const int lane = tid & 31;
    const int tx = blockIdx.x, ty = blockIdx.y, b = blockIdx.z;
    const int gi0 = ty * TILE - HALO;
    const int gj0 = tx * TILE - HALO;            // multiple of 4
    const int colbase = gj0 + lane * 4;          // global col of this lane's elem 0
    const int cb = min(max(colbase, 0), WW - 4); // clamped, stays 16B aligned

    // column in-image mask (constant over rows)
    float4 cm;
    cm.x = ((unsigned)(colbase + 0) < WW) ? 1.f : 0.f;
    cm.y = ((unsigned)(colbase + 1) < WW) ? 1.f : 0.f;
    cm.z = ((unsigned)(colbase + 2) < WW) ? 1.f : 0.f;
    cm.w = ((unsigned)(colbase + 3) < WW) ? 1.f : 0.f;

    // ---- load vector field into smem, deinterleave, zero out-of-image ----
    for (int k = tid; k < EXT * EXT / 2; k += NT) {
        int er = k >> 6;              // 64 px-pairs per 128-col row
        int ec = (k & 63) << 1;
        int gr = gi0 + er;
        int gc = gj0 + ec;
        int grc = min(max(gr, 0), HH - 1);
        int gcc = min(max(gc, 0), WW - 2);
        float4 v = *reinterpret_cast<const float4*>(vf + ((size_t)grc * WW + gcc) * 2);
        float mr = ((unsigned)gr < HH) ? 1.f : 0.f;
        float m0 = mr * (((unsigned)gc < WW) ? 1.f : 0.f);
        float m1 = mr * (((unsigned)(gc + 1) < WW) ? 1.f : 0.f);
        sv0[er * EXT + ec]     = v.x * m0;  sv1[er * EXT + ec]     = v.y * m0;
        sv0[er * EXT + ec + 1] = v.z * m1;  sv1[er * EXT + ec + 1] = v.w * m1;
    }

    // ---- init: u = sigmoid(2*o), q = 0 (register resident) ----
    const float* ob = o + (size_t)b * HH * WW;
    float4 u[RPW], q[RPW];
#pragma unroll
    for (int r = 0; r < RPW; r++) {
        int er = w * RPW + r;
        int gr = gi0 + er;
        int grc = min(max(gr, 0), HH - 1);
        float4 o4 = *reinterpret_cast<const float4*>(ob + (size_t)grc * WW + cb);
        float rm = ((unsigned)gr < HH) ? 1.f : 0.f;
        u[r].x = cm.x * rm * sigm(2.f * o4.x);
        u[r].y = cm.y * rm * sigm(2.f * o4.y);
        u[r].z = cm.z * rm * sigm(2.f * o4.z);
        u[r].w = cm.w * rm * sigm(2.f * o4.w);
        q[r] = make_float4(0.f, 0.f, 0.f, 0.f);
    }
    *reinterpret_cast<float4*>(&xu[w * EXT + lane * 4]) = u[0];
    __syncthreads();

    for (int it = 0; it < NITER; it++) {
        const bool last = (it == NITER - 1);

        // ===== q-step: q = max(q - 0.5*((u_dn-u)*vf1 + (u_rt-u)*vf0), 0) =====
        // out-of-image cells: vf==0 in smem -> q stays exactly 0 (no mask needed)
#pragma unroll
        for (int r = 0; r < RPW; r++) {
            int er = w * RPW + r;
            float4 ud;
            if (r < RPW - 1)          ud = u[r + 1];
            else if (w < NWARP - 1)   ud = *reinterpret_cast<float4*>(&xu[(w + 1) * EXT + lane * 4]);
            else                      ud = make_float4(0.f, 0.f, 0.f, 0.f);
            float ur = __shfl_down_sync(0xffffffffu, u[r].x, 1);
            if (lane == 31) ur = 0.f;
            float4 v0 = *reinterpret_cast<float4*>(&sv0[er * EXT + lane * 4]);
            float4 v1 = *reinterpret_cast<float4*>(&sv1[er * EXT + lane * 4]);
            float t;
            t = (ud.x - u[r].x) * v1.x + (u[r].y - u[r].x) * v0.x;
            q[r].x = fmaxf(fmaf(-0.5f, t, q[r].x), 0.f);
            t = (ud.y - u[r].y) * v1.y + (u[r].z - u[r].y) * v0.y;
            q[r].y = fmaxf(fmaf(-0.5f, t, q[r].y), 0.f);
            t = (ud.z - u[r].z) * v1.z + (u[r].w - u[r].z) * v0.z;
            q[r].z = fmaxf(fmaf(-0.5f, t, q[r].z), 0.f);
            t = (ud.w - u[r].w) * v1.w + (ur - u[r].w) * v0.w;
            q[r].w = fmaxf(fmaf(-0.5f, t, q[r].w), 0.f);
        }
        *reinterpret_cast<float4*>(&xq[w * EXT + lane * 4]) = q[RPW - 1];
        __syncthreads();

        // ===== u-step: Tq = div(vf*q); u = sigmoid(2*(o - Tq)) (or final out) =====
        {
            int er0 = w * RPW;
            float4 v1p = *reinterpret_cast<float4*>(&sv1[max(er0 - 1, 0) * EXT + lane * 4]);
            float4 qup;
            if (w > 0) qup = *reinterpret_cast<float4*>(&xq[(w - 1) * EXT + lane * 4]);
            else       qup = make_float4(0.f, 0.f, 0.f, 0.f);
#pragma unroll
            for (int r = 0; r < RPW; r++) {
                int er = er0 + r;
                int gr = gi0 + er;
                int grc = min(max(gr, 0), HH - 1);
                float4 v1 = *reinterpret_cast<float4*>(&sv1[er * EXT + lane * 4]);
                float4 v0 = *reinterpret_cast<float4*>(&sv0[er * EXT + lane * 4]);
                float v0l = __shfl_up_sync(0xffffffffu, v0.w, 1);
                float ql  = __shfl_up_sync(0xffffffffu, q[r].w, 1);
                if (lane == 0) { v0l = 0.f; ql = 0.f; }
                float4 o4 = *reinterpret_cast<const float4*>(ob + (size_t)grc * WW + cb);

                float Tq0 = v1.x * q[r].x - v1p.x * qup.x + v0.x * q[r].x - v0l  * ql;
                float Tq1 = v1.y * q[r].y - v1p.y * qup.y + v0.y * q[r].y - v0.x * q[r].x;
                float Tq2 = v1.z * q[r].z - v1p.z * qup.z + v0.z * q[r].z - v0.y * q[r].y;
                float Tq3 = v1.w * q[r].w - v1p.w * qup.w + v0.w * q[r].w - v0.z * q[r].z;
                float x0 = 2.f * (o4.x - Tq0);
                float x1 = 2.f * (o4.y - Tq1);
                float x2 = 2.f * (o4.z - Tq2);
                float x3 = 2.f * (o4.w - Tq3);

                if (!last) {
                    float rm = ((unsigned)gr < HH) ? 1.f : 0.f;
                    u[r].x = cm.x * rm * sigm(x0);
                    u[r].y = cm.y * rm * sigm(x1);
                    u[r].z = cm.z * rm * sigm(x2);
                    u[r].w = cm.w * rm * sigm(x3);
                } else {
                    // final: out = (o - Tq)/EPS, only the tile's valid center
                    if (er >= HALO && er < HALO + TILE && gr < HH &&
                        lane >= HALO / 4 && lane < (HALO + TILE) / 4 && colbase < WW) {
                        *reinterpret_cast<float4*>(out + (size_t)((b * HH + gr) * WW + colbase)) =
                            make_float4(x0, x1, x2, x3);
                    }
                }
                v1p = v1;
                qup = q[r];
            }
        }
        if (!last) {
            *reinterpret_cast<float4*>(&xu[w * EXT + lane * 4]) = u[0];
        }
        __syncthreads();
    }
}

extern "C" void kernel_launch(void* const* d_in, const int* in_sizes, int n_in,
                              void* d_out, int out_size) {
    const float* o  = (const float*)d_in[0];
    const float* vf = (const float*)d_in[1];
    float* out = (float*)d_out;

    static bool attr_set = false;
    if (!attr_set) {
        cudaFuncSetAttribute(ccs_fused, cudaFuncAttributeMaxDynamicSharedMemorySize,
                             SMEM_BYTES);
        attr_set = true;
    }

    dim3 grid((WW + TILE - 1) / TILE, (HH + TILE - 1) / TILE, BATCH);  // 10 x 10 x 8
    ccs_fused<<<grid, NT, SMEM_BYTES>>>(o, vf, out);
}

// round 3
// speedup vs baseline: 1.7801x; 1.2247x over previous
#include <cuda_runtime.h>

#define BATCH 8
#define HH 1024
#define WW 1024

#define TILE 104          // valid output span per tile dim
#define HALO 12           // >= 10 needed; 12 keeps float4 alignment
#define EXT  128          // TILE + 2*HALO
#define NWARP 16
#define RPW  8            // rows per warp (NWARP*RPW == EXT)
#define NT   512
#define NITER 10

#define SMEM_BYTES ((2*EXT*EXT + 2*NWARP*EXT) * 4)

__device__ __forceinline__ float sigm(float x) {
    return __fdividef(1.0f, 1.0f + __expf(-x));
}

__global__ void __launch_bounds__(NT, 1)
ccs_fused(const float* __restrict__ o, const float* __restrict__ vf,
          float* __restrict__ out) {
    extern __shared__ float sm[];
    float* sv0 = sm;                    // vf0 [EXT][EXT] (zeroed outside image)
    float* sv1 = sm + EXT * EXT;        // vf1 [EXT][EXT]
    float* xu  = sm + 2 * EXT * EXT;    // per-warp u top-row exchange [NWARP][EXT]
    float* xq  = xu + NWARP * EXT;      // per-warp q bottom-row exchange

    const int tid  = threadIdx.x;
    const int w    = tid >> 5;
    const int lane = tid & 31;
    const int tx = blockIdx.x, ty = blockIdx.y, b = blockIdx.z;
    const int gi0 = ty * TILE - HALO;
    const int gj0 = tx * TILE - HALO;            // multiple of 4
    const int colbase = gj0 + lane * 4;          // global col of this lane's elem 0
    const int cb = min(max(colbase, 0), WW - 4); // clamped, stays 16B aligned

    // column in-image mask (constant over rows)
    float4 cm;
    cm.x = ((unsigned)(colbase + 0) < WW) ? 1.f : 0.f;
    cm.y = ((unsigned)(colbase + 1) < WW) ? 1.f : 0.f;
    cm.z = ((unsigned)(colbase + 2) < WW) ? 1.f : 0.f;
    cm.w = ((unsigned)(colbase + 3) < WW) ? 1.f : 0.f;

    // ---- load vector field into smem, deinterleave, zero out-of-image ----
    for (int k = tid; k < EXT * EXT / 2; k += NT) {
        int er = k >> 6;              // 64 px-pairs per 128-col row
        int ec = (k & 63) << 1;
        int gr = gi0 + er;
        int gc = gj0 + ec;
        int grc = min(max(gr, 0), HH - 1);
        int gcc = min(max(gc, 0), WW - 2);
        float4 v = *reinterpret_cast<const float4*>(vf + ((size_t)grc * WW + gcc) * 2);
        float mr = ((unsigned)gr < HH) ? 1.f : 0.f;
        float m0 = mr * (((unsigned)gc < WW) ? 1.f : 0.f);
        float m1 = mr * (((unsigned)(gc + 1) < WW) ? 1.f : 0.f);
        sv0[er * EXT + ec]     = v.x * m0;  sv1[er * EXT + ec]     = v.y * m0;
        sv0[er * EXT + ec + 1] = v.z * m1;  sv1[er * EXT + ec + 1] = v.w * m1;
    }

    // ---- init: u = sigmoid(2*o), q = 0 (register resident) ----
    const float* ob = o + (size_t)b * HH * WW;
    float4 u[RPW], q[RPW];
#pragma unroll
    for (int r = 0; r < RPW; r++) {
        int er = w * RPW + r;
        int gr = gi0 + er;
        int grc = min(max(gr, 0), HH - 1);
        float4 o4 = *reinterpret_cast<const float4*>(ob + (size_t)grc * WW + cb);
        float rm = ((unsigned)gr < HH) ? 1.f : 0.f;
        u[r].x = cm.x * rm * sigm(2.f * o4.x);
        u[r].y = cm.y * rm * sigm(2.f * o4.y);
        u[r].z = cm.z * rm * sigm(2.f * o4.z);
        u[r].w = cm.w * rm * sigm(2.f * o4.w);
        q[r] = make_float4(0.f, 0.f, 0.f, 0.f);
    }
    *reinterpret_cast<float4*>(&xu[w * EXT + lane * 4]) = u[0];
    __syncthreads();

    for (int it = 0; it < NITER; it++) {
        const bool last = (it == NITER - 1);

        // ===== q-step: q = max(q - 0.5*((u_dn-u)*vf1 + (u_rt-u)*vf0), 0) =====
        // out-of-image cells: vf==0 in smem -> q stays exactly 0 (no mask needed)
#pragma unroll
        for (int r = 0; r < RPW; r++) {
            int er = w * RPW + r;
            float4 ud;
            if (r < RPW - 1)          ud = u[r + 1];
            else if (w < NWARP - 1)   ud = *reinterpret_cast<float4*>(&xu[(w + 1) * EXT + lane * 4]);
            else                      ud = make_float4(0.f, 0.f, 0.f, 0.f);
            float ur = __shfl_down_sync(0xffffffffu, u[r].x, 1);
            if (lane == 31) ur = 0.f;
            float4 v0 = *reinterpret_cast<float4*>(&sv0[er * EXT + lane * 4]);
            float4 v1 = *reinterpret_cast<float4*>(&sv1[er * EXT + lane * 4]);
            float t;
            t = (ud.x - u[r].x) * v1.x + (u[r].y - u[r].x) * v0.x;
            q[r].x = fmaxf(fmaf(-0.5f, t, q[r].x), 0.f);
            t = (ud.y - u[r].y) * v1.y + (u[r].z - u[r].y) * v0.y;
            q[r].y = fmaxf(fmaf(-0.5f, t, q[r].y), 0.f);
            t = (ud.z - u[r].z) * v1.z + (u[r].w - u[r].z) * v0.z;
            q[r].z = fmaxf(fmaf(-0.5f, t, q[r].z), 0.f);
            t = (ud.w - u[r].w) * v1.w + (ur - u[r].w) * v0.w;
            q[r].w = fmaxf(fmaf(-0.5f, t, q[r].w), 0.f);
        }
        *reinterpret_cast<float4*>(&xq[w * EXT + lane * 4]) = q[RPW - 1];
        __syncthreads();

        // ===== u-step: Tq = div(vf*q); u = sigmoid(2*(o - Tq)) (or final out) =====
        {
            int er0 = w * RPW;
            float4 v1p = *reinterpret_cast<float4*>(&sv1[max(er0 - 1, 0) * EXT + lane * 4]);
            float4 qup;
            if (w > 0) qup = *reinterpret_cast<float4*>(&xq[(w - 1) * EXT + lane * 4]);
            else       qup = make_float4(0.f, 0.f, 0.f, 0.f);
#pragma unroll
            for (int r = 0; r < RPW; r++) {
                int er = er0 + r;
                int gr = gi0 + er;
                int grc = min(max(gr, 0), HH - 1);
                float4 v1 = *reinterpret_cast<float4*>(&sv1[er * EXT + lane * 4]);
                float4 v0 = *reinterpret_cast<float4*>(&sv0[er * EXT + lane * 4]);
                float v0l = __shfl_up_sync(0xffffffffu, v0.w, 1);
                float ql  = __shfl_up_sync(0xffffffffu, q[r].w, 1);
                if (lane == 0) { v0l = 0.f; ql = 0.f; }
                float4 o4 = *reinterpret_cast<const float4*>(ob + (size_t)grc * WW + cb);

                float Tq0 = v1.x * q[r].x - v1p.x * qup.x + v0.x * q[r].x - v0l  * ql;
                float Tq1 = v1.y * q[r].y - v1p.y * qup.y + v0.y * q[r].y - v0.x * q[r].x;
                float Tq2 = v1.z * q[r].z - v1p.z * qup.z + v0.z * q[r].z - v0.y * q[r].y;
                float Tq3 = v1.w * q[r].w - v1p.w * qup.w + v0.w * q[r].w - v0.z * q[r].z;
                float x0 = 2.f * (o4.x - Tq0);
                float x1 = 2.f * (o4.y - Tq1);
                float x2 = 2.f * (o4.z - Tq2);
                float x3 = 2.f * (o4.w - Tq3);

                if (!last) {
                    float rm = ((unsigned)gr < HH) ? 1.f : 0.f;
                    u[r].x = cm.x * rm * sigm(x0);
                    u[r].y = cm.y * rm * sigm(x1);
                    u[r].z = cm.z * rm * sigm(x2);
                    u[r].w = cm.w * rm * sigm(x3);
                } else {
                    // final: out = (o - Tq)/EPS, only the tile's valid center
                    if (er >= HALO && er < HALO + TILE && gr < HH &&
                        lane >= HALO / 4 && lane < (HALO + TILE) / 4 && colbase < WW) {
                        *reinterpret_cast<float4*>(out + (size_t)((b * HH + gr) * WW + colbase)) =
                            make_float4(x0, x1, x2, x3);
                    }
                }
                v1p = v1;
                qup = q[r];
            }
        }
        if (!last) {
            *reinterpret_cast<float4*>(&xu[w * EXT + lane * 4]) = u[0];
        }
        __syncthreads();
    }
}

extern "C" void kernel_launch(void* const* d_in, const int* in_sizes, int n_in,
                              void* d_out, int out_size) {
    const float* o  = (const float*)d_in[0];
    const float* vf = (const float*)d_in[1];
    float* out = (float*)d_out;

    static bool attr_set = false;
    if (!attr_set) {
        cudaFuncSetAttribute(ccs_fused, cudaFuncAttributeMaxDynamicSharedMemorySize,
                             SMEM_BYTES);
        attr_set = true;
    }

    dim3 grid((WW + TILE - 1) / TILE, (HH + TILE - 1) / TILE, BATCH);  // 10 x 10 x 8
    ccs_fused<<<grid, NT, SMEM_BYTES>>>(o, vf, out);
}